// round 10
// baseline (speedup 1.0000x reference)
#include <cuda_runtime.h>
#include <cuda_fp16.h>
#include <cstdint>

#define NB 16
#define NT_ 2048
#define ND 100
#define NG 2
#define NQ 4
#define NK 1024
#define DG 50
#define CD 50
#define NTOK (NB*NT_)
#define TILE_T 128
#define NTILES (NTOK/TILE_T)
#define KP 112                     // packed K: 100 split + 3 norm + 9 pad
#define NCHUNK 128
#define NCH (NK/NCHUNK)            // 8
#define CHUNK_B (NCHUNK*KP*2)      // 28672 bytes
#define CHUNK_V (CHUNK_B/16)       // 1792

#define OFF_QUANT 0
#define OFF_LOSS  (NTOK*ND)
#define OFF_COMMIT (OFF_LOSS+NTOK)
#define OFF_RECON (OFF_COMMIT+1)

// smem byte offsets
#define RS_B 0                     // 128x50 f32 = 25600
#define QS_B 25600                 // 25600
#define A_B  51200                 // 128x112 fp16 = 28672
#define B_B  79872                 // 2x28672 = 57344
#define T2_B 137216                // 128x4 int2 = 4096
#define IDX_B 141312               // 512
#define SMEM_B 141824

__device__ __half g_Bpack[NG*NQ*NK*KP];   // packed codebooks (1.84 MB)
__device__ float g_cc[NG*NQ*NK];
__device__ float g_commit[NG*NQ];

__device__ __forceinline__ uint32_t smem_u32(const void* p){
    uint32_t a; asm("{ .reg .u64 t; cvta.to.shared.u64 t, %1; cvt.u32.u64 %0, t; }":"=r"(a):"l"(p)); return a;
}
__device__ __forceinline__ void cpasync16(uint32_t dst, const void* src){
    asm volatile("cp.async.cg.shared.global [%0], [%1], 16;"
                 :: "r"(dst), "l"(__cvta_generic_to_global(src)) : "memory");
}
__device__ __forceinline__ void cp_commit(){ asm volatile("cp.async.commit_group;" ::: "memory"); }
template<int N> __device__ __forceinline__ void cp_wait(){ asm volatile("cp.async.wait_group %0;" :: "n"(N) : "memory"); }
__device__ __forceinline__ void ldsm_x4(uint32_t (&r)[4], uint32_t addr){
    asm volatile("ldmatrix.sync.aligned.m8n8.x4.shared.b16 {%0,%1,%2,%3}, [%4];"
        : "=r"(r[0]),"=r"(r[1]),"=r"(r[2]),"=r"(r[3]) : "r"(addr));
}
__device__ __forceinline__ void ldsm_x2(uint32_t (&r)[2], uint32_t addr){
    asm volatile("ldmatrix.sync.aligned.m8n8.x2.shared.b16 {%0,%1}, [%2];"
        : "=r"(r[0]),"=r"(r[1]) : "r"(addr));
}
__device__ __forceinline__ void mma16816(float (&d)[4], const uint32_t* a, uint32_t b0, uint32_t b1){
    asm volatile("mma.sync.aligned.m16n8k16.row.col.f32.f16.f16.f32 "
        "{%0,%1,%2,%3}, {%4,%5,%6,%7}, {%8,%9}, {%0,%1,%2,%3};"
        : "+f"(d[0]),"+f"(d[1]),"+f"(d[2]),"+f"(d[3])
        : "r"(a[0]),"r"(a[1]),"r"(a[2]),"r"(a[3]), "r"(b0),"r"(b1));
}

// ---- prep: warp per code; pack B = [bh | bh | cc_hi,cc_mid,cc_lo | 0pad] ----
__global__ void __launch_bounds__(256) prep_kernel(const float* __restrict__ cb){
    int code = blockIdx.x*8 + (threadIdx.x>>5);          // 8192 codes
    int lane = threadIdx.x&31;
    const float* src = cb + (size_t)code*CD;
    __half* dst = g_Bpack + (size_t)code*KP;
#pragma unroll
    for (int s=0;s<2;s++){
        int c = lane + s*32;
        if (c < CD){
            __half h = __float2half_rn(src[c]);
            dst[c]=h; dst[50+c]=h;
        }
    }
    if (lane < 9) dst[103+lane] = __float2half_rn(0.f);
    if (lane == 0){
        float cc = 0.f;
        for (int c=0;c<CD;c++){ float v=src[c]; cc += v*v; }
        __half ch = __float2half_rn(cc);
        float rem = cc - __half2float(ch);
        __half cm = __float2half_rn(rem);
        __half cl = __float2half_rn(rem - __half2float(cm));
        dst[100]=ch; dst[101]=cm; dst[102]=cl;
        g_cc[code] = cc;
        if (code < NG*NQ) g_commit[code] = 0.f;
    }
}

// ---- main: 128 tokens x 1 group per CTA, 256 threads (8 warps) ----
__global__ void __launch_bounds__(256,1)
rvq_main(const float* __restrict__ x, const float* __restrict__ W_in,
         const float* __restrict__ b_in, const float* __restrict__ W_out,
         const float* __restrict__ b_out, const float* __restrict__ cbooks,
         float* __restrict__ out){
    extern __shared__ char smem[];
    float* rS = (float*)(smem+RS_B);
    float* qS = (float*)(smem+QS_B);
    __half* Ah = (__half*)(smem+A_B);
    int2* t2S = (int2*)(smem+T2_B);
    int* idxS = (int*)(smem+IDX_B);
    const uint32_t sbA = smem_u32(smem) + A_B;
    const uint32_t sbB = smem_u32(smem) + B_B;

    const int tid = threadIdx.x, wid = tid>>5, lane = tid&31;
    const int g = blockIdx.y, t0 = blockIdx.x*TILE_T;
    const int tok = tid&127, hl = tid>>7;
    const int m0 = wid*16;

    // prologue: project_in (xS aliases A region; WiS aliases B region)
    float* xS = (float*)Ah; float* WiS = (float*)(smem+B_B);
    for (int i=tid;i<TILE_T*DG;i+=256){ int t=i/DG, d=i%DG; xS[i]=x[(size_t)(t0+t)*ND+g*DG+d]; }
    for (int i=tid;i<DG*CD;i+=256) WiS[i]=W_in[g*DG*CD+i];
    __syncthreads();
    {
        float xr[DG];
#pragma unroll 10
        for (int d=0;d<DG;d++) xr[d]=xS[tok*DG+d];
        float rv[25];
        for (int j=0;j<25;j++){ int c=hl*25+j; float s=b_in[g*CD+c];
#pragma unroll 10
            for (int d=0;d<DG;d++) s += xr[d]*WiS[d*CD+c];
            rv[j]=s;
        }
        __syncthreads();                       // xS/WiS reads done; A+B regions free
        for (int j=0;j<25;j++){ int c=hl*25+j; rS[tok*CD+c]=rv[j]; qS[tok*CD+c]=0.f; }
        if (tid < 128){                        // A constant cols per token row
            Ah[tid*KP+100]=__float2half_rn(1.f);
            Ah[tid*KP+101]=__float2half_rn(1.f);
            Ah[tid*KP+102]=__float2half_rn(1.f);
            for (int c=103;c<KP;c++) Ah[tid*KP+c]=__float2half_rn(0.f);
        }
    }

    const uint32_t aaddr0 = sbA + (uint32_t)(((m0 + (lane&15))*KP + ((lane>>4)<<3))*2);
    const uint32_t bboff  = (uint32_t)((((lane&7)*KP) + (((lane>>3)&3)<<3))*2);
    const uint32_t bboff7 = (uint32_t)((((lane&7)*KP) + 96 + (((lane>>3)&1)<<3))*2);

    for (int q=0;q<NQ;q++){
        const __half* Bg = g_Bpack + (size_t)(g*NQ+q)*NK*KP;
        const float* cbg = cbooks + (size_t)(g*NQ+q)*NK*CD;
        const float* ccg = g_cc + (g*NQ+q)*NK;

        __syncthreads();                       // prior-stage consumers done
        // prefetch chunk 0 (overlaps A build)
        for (int i=tid;i<CHUNK_V;i+=256) cpasync16(sbB + i*16, (const char*)Bg + i*16);
        cp_commit();

        // A build: [-2r hi | -2r lo]
        for (int j=0;j<25;j++){ int c=hl*25+j;
            float v = -2.f*rS[tok*CD+c];
            __half h = __float2half_rn(v);
            __half l = __float2half_rn(v - __half2float(h));
            Ah[tok*KP+c]=h; Ah[tok*KP+50+c]=l;
        }
        __syncthreads();

        uint32_t af[7][4];
#pragma unroll
        for (int kf=0;kf<7;kf++) ldsm_x4(af[kf], aaddr0 + kf*32);

        float v1l=__int_as_float(0x7f800000), v2l=v1l, v1h=v1l, v2h=v1l;
        int i1l=0,i2l=0,i1h=0,i2h=0;

        for (int nc=0;nc<NCH;nc++){
            cp_wait<0>();
            __syncthreads();                   // chunk nc ready; all past chunk nc-1
            if (nc<NCH-1){
                const char* srcp = (const char*)Bg + (size_t)(nc+1)*CHUNK_B;
                uint32_t db = sbB + ((nc+1)&1)*CHUNK_B;
                for (int i=tid;i<CHUNK_V;i+=256) cpasync16(db + i*16, srcp + i*16);
                cp_commit();
            }

            uint32_t bb  = sbB + (nc&1)*CHUNK_B + bboff;
            uint32_t bb7 = sbB + (nc&1)*CHUNK_B + bboff7;
#pragma unroll
            for (int nf=0;nf<16;nf++){
                float acc[4] = {0.f,0.f,0.f,0.f};
                uint32_t bn = bb + (uint32_t)(nf*8*KP*2);
#pragma unroll
                for (int kfp=0;kfp<3;kfp++){
                    uint32_t b[4];
                    ldsm_x4(b, bn + kfp*64);
                    mma16816(acc, af[2*kfp],   b[0], b[1]);
                    mma16816(acc, af[2*kfp+1], b[2], b[3]);
                }
                { uint32_t b2[2];
                  ldsm_x2(b2, bb7 + (uint32_t)(nf*8*KP*2));
                  mma16816(acc, af[6], b2[0], b2[1]); }

                int k0 = nc*NCHUNK + nf*8 + 2*(lane&3);
                if (acc[0] < v1l){ v2l=v1l;i2l=i1l; v1l=acc[0];i1l=k0; } else if (acc[0] < v2l){ v2l=acc[0];i2l=k0; }
                if (acc[1] < v1l){ v2l=v1l;i2l=i1l; v1l=acc[1];i1l=k0+1; } else if (acc[1] < v2l){ v2l=acc[1];i2l=k0+1; }
                if (acc[2] < v1h){ v2h=v1h;i2h=i1h; v1h=acc[2];i1h=k0; } else if (acc[2] < v2h){ v2h=acc[2];i2h=k0; }
                if (acc[3] < v1h){ v2h=v1h;i2h=i1h; v1h=acc[3];i1h=k0+1; } else if (acc[3] < v2h){ v2h=acc[3];i2h=k0+1; }
            }
        }

        // publish per-lane top-2 (NO quad merge — 8 candidates per token)
        t2S[(m0 + (lane>>2))*4 + (lane&3)]     = make_int2(i1l, i2l);
        t2S[(m0 + 8 + (lane>>2))*4 + (lane&3)] = make_int2(i1h, i2h);
        __syncthreads();

        // exact fp32 rescore of 8 candidates (thread pair per token, 4 each)
        {
            int tk = tid>>1, sel = tid&1;
            int2 p0 = t2S[tk*4 + sel*2];
            int2 p1 = t2S[tk*4 + sel*2 + 1];
            int c0=p0.x, c1=p0.y, c2=p1.x, c3=p1.y;
            const float* r0 = cbg + (size_t)c0*CD;
            const float* r1 = cbg + (size_t)c1*CD;
            const float* r2 = cbg + (size_t)c2*CD;
            const float* r3 = cbg + (size_t)c3*CD;
            float s0=0.f,s1=0.f,s2=0.f,s3=0.f;
#pragma unroll 10
            for (int c=0;c<CD;c++){
                float r = rS[tk*CD+c];
                s0 = fmaf(r, __ldg(r0+c), s0);
                s1 = fmaf(r, __ldg(r1+c), s1);
                s2 = fmaf(r, __ldg(r2+c), s2);
                s3 = fmaf(r, __ldg(r3+c), s3);
            }
            float d0 = fmaf(-2.f,s0,ccg[c0]);
            float d1 = fmaf(-2.f,s1,ccg[c1]);
            float d2 = fmaf(-2.f,s2,ccg[c2]);
            float d3 = fmaf(-2.f,s3,ccg[c3]);
            float bd = d0; int bi = c0;
            if (d1<bd || (d1==bd && c1<bi)){ bd=d1; bi=c1; }
            if (d2<bd || (d2==bd && c2<bi)){ bd=d2; bi=c2; }
            if (d3<bd || (d3==bd && c3<bi)){ bd=d3; bi=c3; }
            float od = __shfl_xor_sync(0xffffffffu, bd, 1);
            int   oc = __shfl_xor_sync(0xffffffffu, bi, 1);
            if (sel==0)
                idxS[tk] = (od<bd || (od==bd && oc<bi)) ? oc : bi;
        }
        __syncthreads();

        // residual update + qS accumulate + commit loss
        {
            int ii = idxS[tok];
            const float* cr = cbg + (size_t)ii*CD;
            float cl = 0.f;
            for (int j=0;j<25;j++){ int c=hl*25+j;
                float qv = __ldg(cr+c);
                float rr = rS[tok*CD+c];
                float dr2 = qv - rr; cl += dr2*dr2;
                rS[tok*CD+c] = rr - qv;
                qS[tok*CD+c] += qv;
            }
#pragma unroll
            for (int o=16;o;o>>=1) cl += __shfl_down_sync(0xffffffffu, cl, o);
            if (lane==0) atomicAdd(&g_commit[g*NQ+q], cl);
        }
    }

    __syncthreads();
    // project_out (WoS aliases A region)
    float* WoS = (float*)Ah;
    for (int i=tid;i<CD*DG;i+=256) WoS[i]=W_out[g*CD*DG+i];
    __syncthreads();
    for (int j=0;j<25;j++){ int dcol=hl*25+j;
        float s = b_out[g*DG+dcol];
#pragma unroll 10
        for (int c=0;c<CD;c++) s += qS[tok*CD+c]*WoS[c*DG+dcol];
        out[(size_t)(t0+tok)*ND+g*DG+dcol] = s;
    }
}

// ---- finalize: recon/loss/commit ----
__global__ void __launch_bounds__(256)
finalize_kernel(const float* __restrict__ x, float* dst){
    int w = (blockIdx.x*blockDim.x+threadIdx.x)>>5;
    int lane = threadIdx.x&31;
    float cs = 0.f;
#pragma unroll
    for (int i=0;i<NG*NQ;i++) cs += g_commit[i];
    float commit = cs * (1.0f/((float)NTOK*(float)CD*(float)(NG*NQ)));
    if (w < NTOK){
        const float* xr = x + (size_t)w*ND;
        const float* qr = dst + OFF_QUANT + (size_t)w*ND;
        float s = 0.f;
        for (int d=lane;d<ND;d+=32){ float df=xr[d]-qr[d]; s += df*df; }
#pragma unroll
        for (int o=16;o;o>>=1) s += __shfl_down_sync(0xffffffffu, s, o);
        if (lane==0){
            float recon = s*(1.0f/(float)ND);
            dst[OFF_RECON+w] = recon;
            dst[OFF_LOSS+w] = recon + commit;
        }
    }
    if (blockIdx.x==0 && threadIdx.x==0) dst[OFF_COMMIT] = commit;
}

extern "C" void kernel_launch(void* const* d_in, const int* in_sizes, int n_in,
                              void* d_out, int out_size){
    const float* x      = (const float*)d_in[0];
    const float* W_in   = (const float*)d_in[1];
    const float* b_in   = (const float*)d_in[2];
    const float* W_out  = (const float*)d_in[3];
    const float* b_out  = (const float*)d_in[4];
    const float* cbooks = (const float*)d_in[5];
    float* out = (float*)d_out;

    cudaFuncSetAttribute(rvq_main, cudaFuncAttributeMaxDynamicSharedMemorySize, SMEM_B);
    prep_kernel<<<1024,256>>>(cbooks);
    rvq_main<<<dim3(NTILES,NG),256,SMEM_B>>>(x, W_in, b_in, W_out, b_out, cbooks, out);
    finalize_kernel<<<(NTOK*32)/256,256>>>(x, out);
}

// round 13
// speedup vs baseline: 1.1743x; 1.1743x over previous
#include <cuda_runtime.h>
#include <cuda_fp16.h>
#include <cstdint>

#define NB 16
#define NT_ 2048
#define ND 100
#define NG 2
#define NQ 4
#define NK 1024
#define DG 50
#define CD 50
#define NTOK (NB*NT_)
#define TILE_T 128
#define NTILES (NTOK/TILE_T)
#define KP 120                     // row stride: 100 split + 3 norm + 17 pad (240B, conflict-free LDSM)
#define NCHUNK 128
#define NCH (NK/NCHUNK)            // 8
#define CHUNK_B (NCHUNK*KP*2)      // 30720 bytes
#define CHUNK_V (CHUNK_B/16)       // 1920

#define OFF_QUANT 0
#define OFF_LOSS  (NTOK*ND)
#define OFF_COMMIT (OFF_LOSS+NTOK)
#define OFF_RECON (OFF_COMMIT+1)

// smem byte offsets
#define RS_B 0                     // 128x50 f32 = 25600
#define QS_B 25600                 // 25600
#define A_B  51200                 // 128x120 fp16 = 30720
#define B_B  81920                 // 2x30720 = 61440
#define T2_B 143360                // 128x4 int2 = 4096
#define IDX_B 147456               // 512
#define SMEM_B 147968

__device__ __half g_pk[NG*NQ*NK*KP];      // packed codebooks (1.97 MB)
__device__ float g_cc2[NG*NQ*NK];
__device__ float g_cm[NG*NQ];

__device__ __forceinline__ uint32_t smem_u32(const void* p){
    uint32_t a; asm("{ .reg .u64 t; cvta.to.shared.u64 t, %1; cvt.u32.u64 %0, t; }":"=r"(a):"l"(p)); return a;
}
__device__ __forceinline__ void cpa16(uint32_t dst, const void* src){
    asm volatile("cp.async.cg.shared.global [%0], [%1], 16;"
                 :: "r"(dst), "l"(__cvta_generic_to_global(src)) : "memory");
}
__device__ __forceinline__ void cpa_commit(){ asm volatile("cp.async.commit_group;" ::: "memory"); }
template<int N> __device__ __forceinline__ void cpa_wait(){ asm volatile("cp.async.wait_group %0;" :: "n"(N) : "memory"); }
__device__ __forceinline__ void ldsmx4(uint32_t (&r)[4], uint32_t addr){
    asm volatile("ldmatrix.sync.aligned.m8n8.x4.shared.b16 {%0,%1,%2,%3}, [%4];"
        : "=r"(r[0]),"=r"(r[1]),"=r"(r[2]),"=r"(r[3]) : "r"(addr));
}
__device__ __forceinline__ void ldsmx2(uint32_t (&r)[2], uint32_t addr){
    asm volatile("ldmatrix.sync.aligned.m8n8.x2.shared.b16 {%0,%1}, [%2];"
        : "=r"(r[0]),"=r"(r[1]) : "r"(addr));
}
__device__ __forceinline__ void hmma(float (&d)[4], const uint32_t* a, uint32_t b0, uint32_t b1){
    asm volatile("mma.sync.aligned.m16n8k16.row.col.f32.f16.f16.f32 "
        "{%0,%1,%2,%3}, {%4,%5,%6,%7}, {%8,%9}, {%0,%1,%2,%3};"
        : "+f"(d[0]),"+f"(d[1]),"+f"(d[2]),"+f"(d[3])
        : "r"(a[0]),"r"(a[1]),"r"(a[2]),"r"(a[3]), "r"(b0),"r"(b1));
}

// ---- prep: warp per code; pack B = [bh | bh | cc_hi,cc_mid,cc_lo | 0pad] ----
__global__ void __launch_bounds__(256) prep_pack(const float* __restrict__ cb){
    const int code = blockIdx.x*8 + (threadIdx.x>>5);    // 8192 codes
    const int lane = threadIdx.x&31;
    const float* src = cb + (size_t)code*CD;
    __half* dst = g_pk + (size_t)code*KP;
#pragma unroll
    for (int s=0;s<2;s++){
        const int c = lane + s*32;
        if (c < CD){
            const __half h = __float2half_rn(src[c]);
            dst[c]=h; dst[50+c]=h;
        }
    }
    if (lane < 17) dst[103+lane] = __float2half_rn(0.f);  // cols 103..119
    if (lane == 0){
        float cc = 0.f;
        for (int c=0;c<CD;c++){ const float v=src[c]; cc += v*v; }
        const __half ch = __float2half_rn(cc);
        const float rem = cc - __half2float(ch);
        const __half cm = __float2half_rn(rem);
        const __half cl = __float2half_rn(rem - __half2float(cm));
        dst[100]=ch; dst[101]=cm; dst[102]=cl;
        g_cc2[code] = cc;
        if (code < NG*NQ) g_cm[code] = 0.f;
    }
}

// ---- main: 128 tokens x 1 group per CTA, 256 threads (8 warps) ----
__global__ void __launch_bounds__(256,1)
rvq_core(const float* __restrict__ x, const float* __restrict__ W_in,
         const float* __restrict__ b_in, const float* __restrict__ W_out,
         const float* __restrict__ b_out, const float* __restrict__ cbooks,
         float* __restrict__ out){
    extern __shared__ char smem[];
    float* rS = (float*)(smem+RS_B);
    float* qS = (float*)(smem+QS_B);
    __half* Ah = (__half*)(smem+A_B);
    int2* t2S = (int2*)(smem+T2_B);
    int* idxS = (int*)(smem+IDX_B);
    const uint32_t sbA = smem_u32(smem) + A_B;
    const uint32_t sbB = smem_u32(smem) + B_B;

    const int tid = threadIdx.x, wid = tid>>5, lane = tid&31;
    const int g = blockIdx.y, t0 = blockIdx.x*TILE_T;
    const int tok = tid&127, hl = tid>>7;
    const int m0 = wid*16;
    const int cbase = hl*25;

    // prologue: project_in (xS aliases A region; WiS aliases B region)
    float* xS = (float*)Ah; float* WiS = (float*)(smem+B_B);
    for (int i=tid;i<TILE_T*DG;i+=256){ const int t=i/DG, d=i%DG; xS[i]=x[(size_t)(t0+t)*ND+g*DG+d]; }
    for (int i=tid;i<DG*CD;i+=256) WiS[i]=W_in[g*DG*CD+i];
    __syncthreads();
    {
        float xr[DG];
#pragma unroll 10
        for (int d=0;d<DG;d++) xr[d]=xS[tok*DG+d];
        float rv[25];
        for (int j=0;j<25;j++){ const int c=cbase+j; float s=b_in[g*CD+c];
#pragma unroll 10
            for (int d=0;d<DG;d++) s += xr[d]*WiS[d*CD+c];
            rv[j]=s;
        }
        __syncthreads();                       // xS/WiS reads done; A+B regions free
        for (int j=0;j<25;j++){ const int c=cbase+j; rS[tok*CD+c]=rv[j]; qS[tok*CD+c]=0.f; }
        if (tid < 128){                        // A constant cols per token row
            Ah[tid*KP+100]=__float2half_rn(1.f);
            Ah[tid*KP+101]=__float2half_rn(1.f);
            Ah[tid*KP+102]=__float2half_rn(1.f);
            for (int c=103;c<KP;c++) Ah[tid*KP+c]=__float2half_rn(0.f);
        }
    }

    const uint32_t aaddr0 = sbA + (uint32_t)(((m0 + (lane&15))*KP + ((lane>>4)<<3))*2);
    const uint32_t bboff  = (uint32_t)((((lane&7)*KP) + (((lane>>3)&3)<<3))*2);
    const uint32_t bboff7 = (uint32_t)((((lane&7)*KP) + 96 + (((lane>>3)&1)<<3))*2);

    for (int q=0;q<NQ;q++){
        const __half* Bg = g_pk + (size_t)(g*NQ+q)*NK*KP;
        const float* cbg = cbooks + (size_t)(g*NQ+q)*NK*CD;
        const float* ccg = g_cc2 + (g*NQ+q)*NK;

        __syncthreads();                       // prior-stage consumers done
        // prefetch chunk 0 (overlaps A build)
        for (int i=tid;i<CHUNK_V;i+=256) cpa16(sbB + i*16, (const char*)Bg + i*16);
        cpa_commit();

        // A build: [-2r hi | -2r lo]
        for (int j=0;j<25;j++){ const int c=cbase+j;
            const float v = -2.f*rS[tok*CD+c];
            const __half h = __float2half_rn(v);
            const __half l = __float2half_rn(v - __half2float(h));
            Ah[tok*KP+c]=h; Ah[tok*KP+50+c]=l;
        }
        __syncthreads();

        uint32_t af[7][4];
#pragma unroll
        for (int kf=0;kf<7;kf++) ldsmx4(af[kf], aaddr0 + kf*32);

        float v1l=__int_as_float(0x7f800000), v2l=v1l, v1h=v1l, v2h=v1l;
        int i1l=0,i2l=0,i1h=0,i2h=0;

        for (int nc=0;nc<NCH;nc++){
            cpa_wait<0>();
            __syncthreads();                   // chunk nc ready; all past chunk nc-1
            if (nc<NCH-1){
                const char* srcp = (const char*)Bg + (size_t)(nc+1)*CHUNK_B;
                const uint32_t db = sbB + ((nc+1)&1)*CHUNK_B;
                for (int i=tid;i<CHUNK_V;i+=256) cpa16(db + i*16, srcp + i*16);
                cpa_commit();
            }

            const uint32_t bb  = sbB + (nc&1)*CHUNK_B + bboff;
            const uint32_t bb7 = sbB + (nc&1)*CHUNK_B + bboff7;
#pragma unroll
            for (int nf=0;nf<16;nf++){
                float acc[4] = {0.f,0.f,0.f,0.f};
                const uint32_t bn = bb + (uint32_t)(nf*8*KP*2);
#pragma unroll
                for (int kfp=0;kfp<3;kfp++){
                    uint32_t b[4];
                    ldsmx4(b, bn + kfp*64);
                    hmma(acc, af[2*kfp],   b[0], b[1]);
                    hmma(acc, af[2*kfp+1], b[2], b[3]);
                }
                { uint32_t b2[2];
                  ldsmx2(b2, bb7 + (uint32_t)(nf*8*KP*2));
                  hmma(acc, af[6], b2[0], b2[1]); }

                const int k0 = nc*NCHUNK + nf*8 + 2*(lane&3);
                if (acc[0] < v1l){ v2l=v1l;i2l=i1l; v1l=acc[0];i1l=k0; } else if (acc[0] < v2l){ v2l=acc[0];i2l=k0; }
                if (acc[1] < v1l){ v2l=v1l;i2l=i1l; v1l=acc[1];i1l=k0+1; } else if (acc[1] < v2l){ v2l=acc[1];i2l=k0+1; }
                if (acc[2] < v1h){ v2h=v1h;i2h=i1h; v1h=acc[2];i1h=k0; } else if (acc[2] < v2h){ v2h=acc[2];i2h=k0; }
                if (acc[3] < v1h){ v2h=v1h;i2h=i1h; v1h=acc[3];i1h=k0+1; } else if (acc[3] < v2h){ v2h=acc[3];i2h=k0+1; }
            }
        }

        // publish per-lane top-2 (8 candidates per token; disjoint lane subsets)
        t2S[(m0 + (lane>>2))*4 + (lane&3)]     = make_int2(i1l, i2l);
        t2S[(m0 + 8 + (lane>>2))*4 + (lane&3)] = make_int2(i1h, i2h);
        __syncthreads();

        // exact fp32 rescore of 8 candidates (thread pair per token, 4 each)
        {
            const int tk = tid>>1, sel = tid&1;
            const int2 p0 = t2S[tk*4 + sel*2];
            const int2 p1 = t2S[tk*4 + sel*2 + 1];
            const int c0=p0.x, c1=p0.y, c2=p1.x, c3=p1.y;
            const float* r0 = cbg + (size_t)c0*CD;
            const float* r1 = cbg + (size_t)c1*CD;
            const float* r2 = cbg + (size_t)c2*CD;
            const float* r3 = cbg + (size_t)c3*CD;
            float s0=0.f,s1=0.f,s2=0.f,s3=0.f;
#pragma unroll 10
            for (int c=0;c<CD;c++){
                const float r = rS[tk*CD+c];
                s0 = fmaf(r, __ldg(r0+c), s0);
                s1 = fmaf(r, __ldg(r1+c), s1);
                s2 = fmaf(r, __ldg(r2+c), s2);
                s3 = fmaf(r, __ldg(r3+c), s3);
            }
            const float d0 = fmaf(-2.f,s0,ccg[c0]);
            const float d1 = fmaf(-2.f,s1,ccg[c1]);
            const float d2 = fmaf(-2.f,s2,ccg[c2]);
            const float d3 = fmaf(-2.f,s3,ccg[c3]);
            float bd = d0; int bi = c0;
            if (d1<bd || (d1==bd && c1<bi)){ bd=d1; bi=c1; }
            if (d2<bd || (d2==bd && c2<bi)){ bd=d2; bi=c2; }
            if (d3<bd || (d3==bd && c3<bi)){ bd=d3; bi=c3; }
            const float od = __shfl_xor_sync(0xffffffffu, bd, 1);
            const int   oc = __shfl_xor_sync(0xffffffffu, bi, 1);
            if (sel==0)
                idxS[tk] = (od<bd || (od==bd && oc<bi)) ? oc : bi;
        }
        __syncthreads();

        // residual update + qS accumulate + commit loss
        {
            const int ii = idxS[tok];
            const float* cr = cbg + (size_t)ii*CD;
            float cl = 0.f;
            for (int j=0;j<25;j++){ const int c=cbase+j;
                const float qv = __ldg(cr+c);
                const float rr = rS[tok*CD+c];
                const float dr2 = qv - rr; cl += dr2*dr2;
                rS[tok*CD+c] = rr - qv;
                qS[tok*CD+c] += qv;
            }
#pragma unroll
            for (int o=16;o;o>>=1) cl += __shfl_down_sync(0xffffffffu, cl, o);
            if (lane==0) atomicAdd(&g_cm[g*NQ+q], cl);
        }
    }

    __syncthreads();
    // project_out (WoS aliases A region)
    float* WoS = (float*)Ah;
    for (int i=tid;i<CD*DG;i+=256) WoS[i]=W_out[g*CD*DG+i];
    __syncthreads();
    for (int j=0;j<25;j++){ const int dcol=cbase+j;
        float s = b_out[g*DG+dcol];
#pragma unroll 10
        for (int c=0;c<CD;c++) s += qS[tok*CD+c]*WoS[c*DG+dcol];
        out[(size_t)(t0+tok)*ND+g*DG+dcol] = s;
    }
}

// ---- finalize: recon/loss/commit ----
__global__ void __launch_bounds__(256)
loss_final(const float* __restrict__ x, float* dst){
    const int w = (blockIdx.x*blockDim.x+threadIdx.x)>>5;
    const int lane = threadIdx.x&31;
    float cs = 0.f;
#pragma unroll
    for (int i=0;i<NG*NQ;i++) cs += g_cm[i];
    const float commit = cs * (1.0f/((float)NTOK*(float)CD*(float)(NG*NQ)));
    if (w < NTOK){
        const float* xr = x + (size_t)w*ND;
        const float* qr = dst + OFF_QUANT + (size_t)w*ND;
        float s = 0.f;
        for (int d=lane;d<ND;d+=32){ const float df=xr[d]-qr[d]; s += df*df; }
#pragma unroll
        for (int o=16;o;o>>=1) s += __shfl_down_sync(0xffffffffu, s, o);
        if (lane==0){
            const float recon = s*(1.0f/(float)ND);
            dst[OFF_RECON+w] = recon;
            dst[OFF_LOSS+w] = recon + commit;
        }
    }
    if (blockIdx.x==0 && threadIdx.x==0) dst[OFF_COMMIT] = commit;
}

extern "C" void kernel_launch(void* const* d_in, const int* in_sizes, int n_in,
                              void* d_out, int out_size){
    const float* x      = (const float*)d_in[0];
    const float* W_in   = (const float*)d_in[1];
    const float* b_in   = (const float*)d_in[2];
    const float* W_out  = (const float*)d_in[3];
    const float* b_out  = (const float*)d_in[4];
    const float* cbooks = (const float*)d_in[5];
    float* out = (float*)d_out;

    cudaFuncSetAttribute(rvq_core, cudaFuncAttributeMaxDynamicSharedMemorySize, SMEM_B);
    prep_pack<<<1024,256>>>(cbooks);
    rvq_core<<<dim3(NTILES,NG),256,SMEM_B>>>(x, W_in, b_in, W_out, b_out, cbooks, out);
    loss_final<<<(NTOK*32)/256,256>>>(x, out);
}